// round 5
// baseline (speedup 1.0000x reference)
#include <cuda_runtime.h>

// WidthAP: out[b,0,i,h] = sum_{j=0..4} x[b,0,i+j,h] * attn[b,i+j]
// x: (32,1,2052,768) fp32, attn: (32,2052) fp32, out: (32,1,2048,768) fp32.

#define LENGTH   2048
#define WIDTH    5
#define PADDED   (LENGTH + WIDTH - 1)   // 2052
#define BATCH    32
#define HDIM     768
#define H4       (HDIM / 4)             // 192 float4 lanes
#define ITILE    64                     // rows per block -> 1024 CTAs
#define NTILES   (LENGTH / ITILE)       // 32
#define UNROLL   8

__device__ __forceinline__ float4 f4_scale(float4 v, float s) {
    return make_float4(v.x * s, v.y * s, v.z * s, v.w * s);
}
__device__ __forceinline__ float4 f4_add(float4 a, float4 b) {
    return make_float4(a.x + b.x, a.y + b.y, a.z + b.z, a.w + b.w);
}

__global__ __launch_bounds__(H4, 6) void widthap_kernel(
    const float4* __restrict__ x,      // (B, PADDED, H4)
    const float*  __restrict__ attn,   // (B, PADDED)
    float4*       __restrict__ out)    // (B, LENGTH, H4)
{
    const int lane = threadIdx.x;          // 0..191, one float4 column
    const int tile = blockIdx.x;           // 0..31
    const int b    = blockIdx.y;           // 0..31
    const int i0   = tile * ITILE;

    __shared__ float w[ITILE + WIDTH - 1]; // 68 weights
    if (lane < ITILE + WIDTH - 1)
        w[lane] = attn[b * PADDED + i0 + lane];
    __syncthreads();

    const float4* xp = x   + ((long)b * PADDED + i0) * H4 + lane;
    float4*       op = out + ((long)b * LENGTH + i0) * H4 + lane;

    // Prime the 5-deep weighted window (first 4 rows).
    float4 v0 = f4_scale(__ldcs(xp + 0 * H4), w[0]);
    float4 v1 = f4_scale(__ldcs(xp + 1 * H4), w[1]);
    float4 v2 = f4_scale(__ldcs(xp + 2 * H4), w[2]);
    float4 v3 = f4_scale(__ldcs(xp + 3 * H4), w[3]);

    for (int i = 0; i < ITILE; i += UNROLL) {
        // Batch of 8 independent streaming loads (front-batched MLP).
        float4 xv[UNROLL];
        #pragma unroll
        for (int u = 0; u < UNROLL; u++)
            xv[u] = __ldcs(xp + (i + 4 + u) * H4);

        // Compute + store immediately (stores are fire-and-forget; no need
        // to buffer outputs in registers).
        #pragma unroll
        for (int u = 0; u < UNROLL; u++) {
            float4 v4 = f4_scale(xv[u], w[i + 4 + u]);
            __stcs(op + (i + u) * H4,
                   f4_add(f4_add(f4_add(v0, v1), f4_add(v2, v3)), v4));
            v0 = v1; v1 = v2; v2 = v3; v3 = v4;
        }
    }
}

extern "C" void kernel_launch(void* const* d_in, const int* in_sizes, int n_in,
                              void* d_out, int out_size)
{
    const float4* x    = (const float4*)d_in[0];
    const float*  attn = (const float*)d_in[1];
    float4*       out  = (float4*)d_out;

    dim3 grid(NTILES, BATCH);
    widthap_kernel<<<grid, H4>>>(x, attn, out);
}

// round 6
// speedup vs baseline: 1.1076x; 1.1076x over previous
#include <cuda_runtime.h>

// WidthAP: out[b,0,i,h] = sum_{j=0..4} x[b,0,i+j,h] * attn[b,i+j]
// x: (32,1,2052,768) fp32, attn: (32,2052) fp32, out: (32,1,2048,768) fp32.

#define LENGTH   2048
#define WIDTH    5
#define PADDED   (LENGTH + WIDTH - 1)   // 2052
#define BATCH    32
#define HDIM     768
#define H4       (HDIM / 4)             // 192 float4 lanes
#define ITILE    128                    // rows per block -> 512 CTAs, 3% halo traffic
#define NTILES   (LENGTH / ITILE)       // 16
#define UNROLL   16                     // front-batched LDG.128 burst depth

__device__ __forceinline__ float4 f4_scale(float4 v, float s) {
    return make_float4(v.x * s, v.y * s, v.z * s, v.w * s);
}
__device__ __forceinline__ float4 f4_add(float4 a, float4 b) {
    return make_float4(a.x + b.x, a.y + b.y, a.z + b.z, a.w + b.w);
}

__global__ __launch_bounds__(H4) void widthap_kernel(
    const float4* __restrict__ x,      // (B, PADDED, H4)
    const float*  __restrict__ attn,   // (B, PADDED)
    float4*       __restrict__ out)    // (B, LENGTH, H4)
{
    const int lane = threadIdx.x;          // 0..191, one float4 column
    const int tile = blockIdx.x;           // 0..15
    const int b    = blockIdx.y;           // 0..31
    const int i0   = tile * ITILE;

    __shared__ float w[ITILE + WIDTH - 1]; // 132 weights
    for (int k = lane; k < ITILE + WIDTH - 1; k += blockDim.x)
        w[k] = attn[b * PADDED + i0 + k];
    __syncthreads();

    const float4* xp = x   + ((long)b * PADDED + i0) * H4 + lane;
    float4*       op = out + ((long)b * LENGTH + i0) * H4 + lane;

    // Prime the 5-deep weighted window (first 4 rows).
    float4 v0 = f4_scale(__ldcs(xp + 0 * H4), w[0]);
    float4 v1 = f4_scale(__ldcs(xp + 1 * H4), w[1]);
    float4 v2 = f4_scale(__ldcs(xp + 2 * H4), w[2]);
    float4 v3 = f4_scale(__ldcs(xp + 3 * H4), w[3]);

    for (int i = 0; i < ITILE; i += UNROLL) {
        // 16 independent streaming loads, front-batched (MLP_p1 = 16).
        float4 xv[UNROLL];
        #pragma unroll
        for (int u = 0; u < UNROLL; u++)
            xv[u] = __ldcs(xp + (i + 4 + u) * H4);

        // Compute + store immediately; loads above are already in flight.
        #pragma unroll
        for (int u = 0; u < UNROLL; u++) {
            float4 v4 = f4_scale(xv[u], w[i + 4 + u]);
            __stcs(op + (i + u) * H4,
                   f4_add(f4_add(f4_add(v0, v1), f4_add(v2, v3)), v4));
            v0 = v1; v1 = v2; v2 = v3; v3 = v4;
        }
    }
}

extern "C" void kernel_launch(void* const* d_in, const int* in_sizes, int n_in,
                              void* d_out, int out_size)
{
    const float4* x    = (const float4*)d_in[0];
    const float*  attn = (const float*)d_in[1];
    float4*       out  = (float4*)d_out;

    dim3 grid(NTILES, BATCH);
    widthap_kernel<<<grid, H4>>>(x, attn, out);
}

// round 7
// speedup vs baseline: 1.2037x; 1.0867x over previous
#include <cuda_runtime.h>

// WidthAP: out[b,0,i,h] = sum_{j=0..4} x[b,0,i+j,h] * attn[b,i+j]
// x: (32,1,2052,768) fp32, attn: (32,2052) fp32, out: (32,1,2048,768) fp32.
//
// Software-pipelined: batch k+1's 8 loads are issued before batch k is
// consumed, so computes never wait on DRAM and each warp keeps >=8
// independent LDG.128s in flight at all times.

#define LENGTH   2048
#define WIDTH    5
#define PADDED   (LENGTH + WIDTH - 1)   // 2052
#define BATCH    32
#define HDIM     768
#define H4       (HDIM / 4)             // 192 float4 lanes
#define ITILE    64                     // rows per block -> 1024 CTAs
#define NTILES   (LENGTH / ITILE)       // 32
#define UB       8                      // batch depth

__device__ __forceinline__ float4 f4_scale(float4 v, float s) {
    return make_float4(v.x * s, v.y * s, v.z * s, v.w * s);
}
__device__ __forceinline__ float4 f4_add(float4 a, float4 b) {
    return make_float4(a.x + b.x, a.y + b.y, a.z + b.z, a.w + b.w);
}

__global__ __launch_bounds__(H4) void widthap_kernel(
    const float4* __restrict__ x,      // (B, PADDED, H4)
    const float*  __restrict__ attn,   // (B, PADDED)
    float4*       __restrict__ out)    // (B, LENGTH, H4)
{
    const int lane = threadIdx.x;          // 0..191, one float4 column
    const int tile = blockIdx.x;           // 0..31
    const int b    = blockIdx.y;           // 0..31
    const int i0   = tile * ITILE;

    __shared__ float w[ITILE + WIDTH - 1]; // 68 weights
    if (lane < ITILE + WIDTH - 1)
        w[lane] = attn[b * PADDED + i0 + lane];
    __syncthreads();

    const float4* xp = x   + ((long)b * PADDED + i0) * H4 + lane;
    float4*       op = out + ((long)b * LENGTH + i0) * H4 + lane;

    // Prime the 5-deep weighted window (rows 0..3).
    float4 v0 = f4_scale(__ldcs(xp + 0 * H4), w[0]);
    float4 v1 = f4_scale(__ldcs(xp + 1 * H4), w[1]);
    float4 v2 = f4_scale(__ldcs(xp + 2 * H4), w[2]);
    float4 v3 = f4_scale(__ldcs(xp + 3 * H4), w[3]);

    // Prime first batch: x rows 4..11 (feeding outputs 0..7).
    float4 xa[UB], xb[UB];
    #pragma unroll
    for (int u = 0; u < UB; u++)
        xa[u] = __ldcs(xp + (4 + u) * H4);

    // Outer loop unrolled x2 so xa/xb alternate without register copies.
    // i = 0, 16, 32, 48.
    for (int i = 0; i < ITILE; i += 2 * UB) {
        // Prefetch batch for outputs i+8..i+15 (x rows i+12..i+19).
        // Always in-range: i <= ITILE-16 -> last rows ITILE-4..ITILE+3.
        #pragma unroll
        for (int u = 0; u < UB; u++)
            xb[u] = __ldcs(xp + (i + 12 + u) * H4);

        // Consume xa -> outputs i..i+7 (data landed long ago; no stall).
        #pragma unroll
        for (int u = 0; u < UB; u++) {
            float4 v4 = f4_scale(xa[u], w[i + 4 + u]);
            __stcs(op + (i + u) * H4,
                   f4_add(f4_add(f4_add(v0, v1), f4_add(v2, v3)), v4));
            v0 = v1; v1 = v2; v2 = v3; v3 = v4;
        }

        // Prefetch batch for outputs i+16..i+23 (x rows i+20..i+27),
        // unless this is the final pair of batches.
        if (i + 2 * UB < ITILE) {
            #pragma unroll
            for (int u = 0; u < UB; u++)
                xa[u] = __ldcs(xp + (i + 20 + u) * H4);
        }

        // Consume xb -> outputs i+8..i+15.
        #pragma unroll
        for (int u = 0; u < UB; u++) {
            float4 v4 = f4_scale(xb[u], w[i + 12 + u]);
            __stcs(op + (i + 8 + u) * H4,
                   f4_add(f4_add(f4_add(v0, v1), f4_add(v2, v3)), v4));
            v0 = v1; v1 = v2; v2 = v3; v3 = v4;
        }
    }
}

extern "C" void kernel_launch(void* const* d_in, const int* in_sizes, int n_in,
                              void* d_out, int out_size)
{
    const float4* x    = (const float4*)d_in[0];
    const float*  attn = (const float*)d_in[1];
    float4*       out  = (float4*)d_out;

    dim3 grid(NTILES, BATCH);
    widthap_kernel<<<grid, H4>>>(x, attn, out);
}